// round 15
// baseline (speedup 1.0000x reference)
#include <cuda_runtime.h>
#include <cuda_fp16.h>
#include <math.h>
#include <stdint.h>

#define BATCH 16384
#define QDIM  1024
#define N1    4096
#define N2    2048

// ---------------------------------------------------------------------------
// Scratch (device globals — allocation-free rule)
// ---------------------------------------------------------------------------
__device__ float  g_stats[2][9];
__device__ __half g_h1 [(size_t)BATCH * N1];
__device__ float  g_h2 [(size_t)BATCH * N2];
__device__ __half g_h2t[(size_t)BATCH * N2];
__device__ __half g_p  [(size_t)BATCH * N2];
__device__ float  g_amp[(size_t)BATCH * QDIM];
__device__ float  g_phs[(size_t)BATCH * QDIM];
__device__ __half g_qs [(size_t)BATCH * QDIM];
__device__ __half g_v  [(size_t)BATCH * QDIM];
__device__ __half g_w2 [(size_t)N2 * N1];
__device__ __half g_w3 [(size_t)QDIM * N2];
__device__ __half g_pw2[(size_t)QDIM * N2];
__device__ __half g_wv [(size_t)QDIM * QDIM];
__device__ __half g_wo [(size_t)QDIM * QDIM];

// ---------------------------------------------------------------------------
// Helpers
// ---------------------------------------------------------------------------
__device__ __forceinline__ uint32_t smem_u32(const void* p) {
    uint32_t a;
    asm("{ .reg .u64 t; cvta.to.shared.u64 t, %1; cvt.u32.u64 %0, t; }"
        : "=r"(a) : "l"(p));
    return a;
}
__device__ __forceinline__ size_t gaddr(const void* p) {
    size_t r;
    asm("cvta.to.global.u64 %0, %1;" : "=l"(r) : "l"(p));
    return r;
}
static __device__ __forceinline__ uint32_t swz128(uint32_t x) {
    return x ^ ((x >> 3) & 0x70);
}

// ---------------------------------------------------------------------------
// Single-pass fp16 GEMM via mma.sync (HMMA):
//   C[M,N] = A[M,K] @ B[N,K]^T + bias, fp32 accumulate.
// CTA 128x256, 8 warps in 2(m) x 4(n), WARP TILE 64x64 (32 MMAs / 8 loads per
// ks-step). BK=64, 3-stage cp.async ring (144 KB, 1 CTA/SM), single barrier
// per K-chunk (3-stage ring makes the bottom barrier redundant).
// EPI: 0 = fp32 out, 1 = tanh fp32 out, 2 = fp16 out.
// ---------------------------------------------------------------------------
#define BM 128
#define BN 256
#define BK 64
#define A_TILE_B (BM * BK * 2)     // 16384
#define B_TILE_B (BN * BK * 2)     // 32768
#define STG_B    (A_TILE_B + B_TILE_B)  // 49152
#define NSTG     3
#define SMEM_F   (NSTG * STG_B)    // 147456

template <int EPI>
__global__ __launch_bounds__(256, 1)
void gemm_fp16(const __half* __restrict__ A, const __half* __restrict__ B,
               const float* __restrict__ bias,
               float* __restrict__ Cf, __half* __restrict__ Ch,
               int Ntot, int K) {
    extern __shared__ char smem[];
    uint32_t sbase = smem_u32(smem);
    int tid = threadIdx.x, lane = tid & 31, wid = tid >> 5;
    int bm = blockIdx.y * BM, bn = blockIdx.x * BN;
    int wm = (wid >> 2) * 64, wn = (wid & 3) * 64;

    const int nIt = K / BK;

    float acc[32][4];
#pragma unroll
    for (int i = 0; i < 32; i++)
#pragma unroll
        for (int j = 0; j < 4; j++) acc[i][j] = 0.f;

    int lrow = tid >> 3;        // 0..31 base row; +32*i
    int lcol = (tid & 7) * 16;  // byte column within 128B row

    auto issue_stage = [&](int it, int stage) {
        uint32_t sb = sbase + stage * STG_B;
        int kb = it * BK + (tid & 7) * 8;   // element offset in K
#pragma unroll
        for (int i = 0; i < 4; i++) {       // A: 128 rows
            int row = lrow + i * 32;
            uint32_t off = swz128((uint32_t)(row * 128 + lcol));
            size_t g0 = gaddr(A + (size_t)(bm + row) * K + kb);
            asm volatile("cp.async.cg.shared.global [%0], [%1], 16;"
                         :: "r"(sb + off), "l"(g0));
        }
#pragma unroll
        for (int i = 0; i < 8; i++) {       // B: 256 rows
            int row = lrow + i * 32;
            uint32_t off = swz128((uint32_t)(row * 128 + lcol));
            size_t g1 = gaddr(B + (size_t)(bn + row) * K + kb);
            asm volatile("cp.async.cg.shared.global [%0], [%1], 16;"
                         :: "r"(sb + A_TILE_B + off), "l"(g1));
        }
        asm volatile("cp.async.commit_group;" ::: "memory");
    };

    issue_stage(0, 0);
    if (nIt > 1) issue_stage(1, 1);

    for (int it = 0; it < nIt; it++) {
        if (it + 1 < nIt) {
            asm volatile("cp.async.wait_group 1;" ::: "memory");
        } else {
            asm volatile("cp.async.wait_group 0;" ::: "memory");
        }
        __syncthreads();     // stage `it` visible; all threads done with it-1
        if (it + 2 < nIt) issue_stage(it + 2, (it + 2) % NSTG);  // slot (it-1)%3 — safe

        uint32_t sA = sbase + (it % NSTG) * STG_B;
        uint32_t sB = sA + A_TILE_B;

#pragma unroll
        for (int ks = 0; ks < 4; ks++) {
            uint32_t a[4][4], b[8][2];
#pragma unroll
            for (int mi = 0; mi < 4; mi++) {
                int row = wm + mi * 16 + (lane & 15);
                uint32_t off = swz128((uint32_t)(row * 128 + ks * 32 + (lane >> 4) * 16));
                asm volatile("ldmatrix.sync.aligned.m8n8.x4.shared.b16 {%0,%1,%2,%3}, [%4];"
                             : "=r"(a[mi][0]), "=r"(a[mi][1]), "=r"(a[mi][2]), "=r"(a[mi][3])
                             : "r"(sA + off));
            }
            // B: x4 pairing two n-groups per load (4 loads cover 8 n-groups)
#pragma unroll
            for (int np = 0; np < 4; np++) {
                int row = wn + np * 16 + ((lane >> 4) & 1) * 8 + (lane & 7);
                uint32_t off = swz128((uint32_t)(row * 128 + ks * 32 + ((lane >> 3) & 1) * 16));
                asm volatile("ldmatrix.sync.aligned.m8n8.x4.shared.b16 {%0,%1,%2,%3}, [%4];"
                             : "=r"(b[2 * np][0]), "=r"(b[2 * np][1]),
                               "=r"(b[2 * np + 1][0]), "=r"(b[2 * np + 1][1])
                             : "r"(sB + off));
            }
#pragma unroll
            for (int mi = 0; mi < 4; mi++)
#pragma unroll
                for (int ni = 0; ni < 8; ni++) {
                    float* c = acc[mi * 8 + ni];
                    asm volatile(
                        "mma.sync.aligned.m16n8k16.row.col.f32.f16.f16.f32 "
                        "{%0,%1,%2,%3}, {%4,%5,%6,%7}, {%8,%9}, {%0,%1,%2,%3};"
                        : "+f"(c[0]), "+f"(c[1]), "+f"(c[2]), "+f"(c[3])
                        : "r"(a[mi][0]), "r"(a[mi][1]), "r"(a[mi][2]), "r"(a[mi][3]),
                          "r"(b[ni][0]), "r"(b[ni][1]));
                }
        }
        // no bottom barrier (3-stage ring)
    }

    // epilogue
    int mb = bm + wm, nb = bn + wn;
#pragma unroll
    for (int mi = 0; mi < 4; mi++)
#pragma unroll
        for (int ni = 0; ni < 8; ni++) {
            float* c = acc[mi * 8 + ni];
            int r0 = mb + mi * 16 + (lane >> 2);
            int c0 = nb + ni * 8 + (lane & 3) * 2;
            float b0 = __ldg(bias + c0), b1 = __ldg(bias + c0 + 1);
            float y0 = c[0] + b0, y1 = c[1] + b1;
            float y2 = c[2] + b0, y3 = c[3] + b1;
            if (EPI == 1) {
                y0 = tanhf(y0); y1 = tanhf(y1); y2 = tanhf(y2); y3 = tanhf(y3);
            }
            if (EPI == 2) {
                __half2 p0; p0.x = __float2half(y0); p0.y = __float2half(y1);
                __half2 p1; p1.x = __float2half(y2); p1.y = __float2half(y3);
                *(__half2*)(Ch + (size_t)r0 * Ntot + c0)       = p0;
                *(__half2*)(Ch + (size_t)(r0 + 8) * Ntot + c0) = p1;
            } else {
                *(float2*)(Cf + (size_t)r0 * Ntot + c0)       = make_float2(y0, y1);
                *(float2*)(Cf + (size_t)(r0 + 8) * Ntot + c0) = make_float2(y2, y3);
            }
        }
}

// ---------------------------------------------------------------------------
// Weight convert: fp32 -> fp16 (8 elems/thread, 16B store)
// ---------------------------------------------------------------------------
__global__ void conv_fp16(const float* __restrict__ in, __half* __restrict__ out, int n8) {
    int i = blockIdx.x * blockDim.x + threadIdx.x;
    if (i >= n8) return;
    float4 v0 = *(const float4*)(in + 8 * i);
    float4 v1 = *(const float4*)(in + 8 * i + 4);
    __half2 h[4];
    h[0].x = __float2half(v0.x); h[0].y = __float2half(v0.y);
    h[1].x = __float2half(v0.z); h[1].y = __float2half(v0.w);
    h[2].x = __float2half(v1.x); h[2].y = __float2half(v1.y);
    h[3].x = __float2half(v1.z); h[3].y = __float2half(v1.w);
    *(uint4*)(out + 8 * i) = *(uint4*)h;
}

// ---------------------------------------------------------------------------
// Moments for the F=2 closed-form LN
// ---------------------------------------------------------------------------
__global__ void moments_kernel(const float* __restrict__ W,
                               const float* __restrict__ bv, int N, int which) {
    int tid = threadIdx.x;
    double acc[9];
#pragma unroll
    for (int q = 0; q < 9; q++) acc[q] = 0.0;
    for (int j = tid; j < N; j += 256) {
        double w0 = W[2 * j], w1 = W[2 * j + 1], b = bv[j];
        acc[0] += w0;      acc[1] += w1;      acc[2] += b;
        acc[3] += w0 * w0; acc[4] += w1 * w1; acc[5] += b * b;
        acc[6] += w0 * w1; acc[7] += w0 * b;  acc[8] += w1 * b;
    }
    __shared__ double sd[256];
    for (int q = 0; q < 9; q++) {
        sd[tid] = acc[q];
        __syncthreads();
        for (int s = 128; s > 0; s >>= 1) {
            if (tid < s) sd[tid] += sd[tid + s];
            __syncthreads();
        }
        if (tid == 0) g_stats[which][q] = (float)(sd[0] / N);
        __syncthreads();
    }
}

// ---------------------------------------------------------------------------
// Layer-1 (elementwise, closed-form LN) -> fp16. act: 0=gelu, 1=silu
// ---------------------------------------------------------------------------
__global__ void layer1_kernel(const float* __restrict__ x, const float* __restrict__ W,
                              const float* __restrict__ bv, const float* __restrict__ gam,
                              const float* __restrict__ bet,
                              __half* __restrict__ oh,
                              int N, int which, int act) {
    int nv = N >> 2;
    int i = blockIdx.x * blockDim.x + threadIdx.x;
    if (i >= BATCH * nv) return;
    int b = i / nv;
    int j = (i - b * nv) << 2;

    float x0 = __ldg(x + 2 * b), x1 = __ldg(x + 2 * b + 1);
    const float* s = g_stats[which];
    float m  = x0 * s[0] + x1 * s[1] + s[2];
    float E2 = x0 * x0 * s[3] + x1 * x1 * s[4] + s[5]
             + 2.f * (x0 * x1 * s[6] + x0 * s[7] + x1 * s[8]);
    float rstd = rsqrtf(fmaxf(E2 - m * m, 0.f) + 1e-5f);

    float4 wA = *(const float4*)(W + 2 * j);
    float4 wB = *(const float4*)(W + 2 * j + 4);
    float4 bb = *(const float4*)(bv + j);
    float4 gg = *(const float4*)(gam + j);
    float4 ee = *(const float4*)(bet + j);

    float y[4];
    y[0] = x0 * wA.x + x1 * wA.y + bb.x;
    y[1] = x0 * wA.z + x1 * wA.w + bb.y;
    y[2] = x0 * wB.x + x1 * wB.y + bb.z;
    y[3] = x0 * wB.z + x1 * wB.w + bb.w;
    float gv[4] = {gg.x, gg.y, gg.z, gg.w};
    float ev[4] = {ee.x, ee.y, ee.z, ee.w};

    __half2 o01, o23;
    float o[4];
#pragma unroll
    for (int q = 0; q < 4; q++) {
        float t = (y[q] - m) * rstd * gv[q] + ev[q];
        if (act == 0) o[q] = 0.5f * t * (1.0f + erff(t * 0.70710678118654752f));
        else          o[q] = t / (1.0f + expf(-t));
    }
    o01.x = __float2half(o[0]); o01.y = __float2half(o[1]);
    o23.x = __float2half(o[2]); o23.y = __float2half(o[3]);
    size_t base = (size_t)b * N + j;
    *(__half2*)(oh + base)     = o01;
    *(__half2*)(oh + base + 2) = o23;
}

// ---------------------------------------------------------------------------
// Row LayerNorm + tanh over N=2048, fp32 in -> fp16 out
// ---------------------------------------------------------------------------
__global__ void ln_tanh_rows(const float* __restrict__ data,
                             const float* __restrict__ gam, const float* __restrict__ bet,
                             __half* __restrict__ oh) {
    const int N = 2048;
    int row = blockIdx.x, tid = threadIdx.x;
    const float* p = data + (size_t)row * N;

    float v[8], s = 0.f, s2 = 0.f;
#pragma unroll
    for (int i = 0; i < 8; i++) {
        float t = p[tid + i * 256];
        v[i] = t; s += t; s2 += t * t;
    }
#pragma unroll
    for (int o = 16; o > 0; o >>= 1) {
        s  += __shfl_down_sync(0xffffffffu, s, o);
        s2 += __shfl_down_sync(0xffffffffu, s2, o);
    }
    __shared__ float sh[2][8];
    __shared__ float mb[2];
    int w = tid >> 5, l = tid & 31;
    if (l == 0) { sh[0][w] = s; sh[1][w] = s2; }
    __syncthreads();
    if (tid == 0) {
        float S = 0.f, S2 = 0.f;
#pragma unroll
        for (int q = 0; q < 8; q++) { S += sh[0][q]; S2 += sh[1][q]; }
        float mean = S / N;
        mb[0] = mean;
        mb[1] = rsqrtf(fmaxf(S2 / N - mean * mean, 0.f) + 1e-5f);
    }
    __syncthreads();
    float mean = mb[0], rstd = mb[1];
    size_t base = (size_t)row * N;
#pragma unroll
    for (int i = 0; i < 8; i++) {
        int c = tid + i * 256;
        float t = tanhf((v[i] - mean) * rstd * gam[c] + bet[c]);
        oh[base + c] = __float2half(t);
    }
}

// ---------------------------------------------------------------------------
// qs mix, fp32 amp/phase in -> fp16 out
// ---------------------------------------------------------------------------
__global__ void qs_kernel(const float* __restrict__ amp, const float* __restrict__ phase,
                          const float* __restrict__ rot_freq, const float* __restrict__ rot_phase,
                          __half* __restrict__ qh) {
    int i = blockIdx.x * blockDim.x + threadIdx.x;
    if (i >= BATCH * (QDIM / 4)) return;
    int j = (i & (QDIM / 4 - 1)) << 2;
    float4 a  = *(const float4*)(amp + (size_t)i * 4);
    float4 ph = *(const float4*)(phase + (size_t)i * 4);
    const float* rf = rot_freq  + (size_t)(4 * QDIM + j) * 3;
    const float* rp = rot_phase + (size_t)(4 * QDIM + j) * 3;
    float av[4] = {a.x, a.y, a.z, a.w};
    float pv[4] = {ph.x, ph.y, ph.z, ph.w};
    float o[4];
#pragma unroll
    for (int q = 0; q < 4; q++) {
        float rx = sinf(av[q] * rf[3 * q + 0] + rp[3 * q + 0]);
        float ry = cosf(pv[q] * rf[3 * q + 1] + rp[3 * q + 1]);
        float rz = tanhf(rp[3 * q + 2]);
        o[q] = (rx + ry + rz) * (1.0f / 3.0f);
    }
    __half2 o01, o23;
    o01.x = __float2half(o[0]); o01.y = __float2half(o[1]);
    o23.x = __float2half(o[2]); o23.y = __float2half(o[3]);
    *(__half2*)(qh + (size_t)i * 4)     = o01;
    *(__half2*)(qh + (size_t)i * 4 + 2) = o23;
}

// ---------------------------------------------------------------------------
// Launch
// ---------------------------------------------------------------------------
static void gemm_run(int epi, const __half* A, const __half* B,
                     const float* bias, float* Cf, __half* Ch, int Ntot, int K) {
    dim3 g(Ntot / BN, BATCH / BM);
    switch (epi) {
    case 0:  gemm_fp16<0><<<g, 256, SMEM_F>>>(A, B, bias, Cf, Ch, Ntot, K); break;
    case 1:  gemm_fp16<1><<<g, 256, SMEM_F>>>(A, B, bias, Cf, Ch, Ntot, K); break;
    default: gemm_fp16<2><<<g, 256, SMEM_F>>>(A, B, bias, Cf, Ch, Ntot, K); break;
    }
}

extern "C" void kernel_launch(void* const* d_in, const int* in_sizes, int n_in,
                              void* d_out, int out_size) {
    const float* x         = (const float*)d_in[0];
    const float* amp_W1    = (const float*)d_in[1];
    const float* amp_b1    = (const float*)d_in[2];
    const float* amp_g1    = (const float*)d_in[3];
    const float* amp_be1   = (const float*)d_in[4];
    const float* amp_W2    = (const float*)d_in[5];
    const float* amp_b2    = (const float*)d_in[6];
    const float* amp_g2    = (const float*)d_in[7];
    const float* amp_be2   = (const float*)d_in[8];
    const float* amp_W3    = (const float*)d_in[9];
    const float* amp_b3    = (const float*)d_in[10];
    const float* ph_W1     = (const float*)d_in[11];
    const float* ph_b1     = (const float*)d_in[12];
    const float* ph_g1     = (const float*)d_in[13];
    const float* ph_be1    = (const float*)d_in[14];
    const float* ph_W2     = (const float*)d_in[15];
    const float* ph_b2     = (const float*)d_in[16];
    const float* rot_freq  = (const float*)d_in[17];
    const float* rot_phase = (const float*)d_in[18];
    const float* attn_in_w = (const float*)d_in[19];
    const float* attn_in_b = (const float*)d_in[20];
    const float* attn_out_w= (const float*)d_in[21];
    const float* attn_out_b= (const float*)d_in[22];
    float* out = (float*)d_out;

    cudaFuncSetAttribute(gemm_fp16<0>, cudaFuncAttributeMaxDynamicSharedMemorySize, SMEM_F);
    cudaFuncSetAttribute(gemm_fp16<1>, cudaFuncAttributeMaxDynamicSharedMemorySize, SMEM_F);
    cudaFuncSetAttribute(gemm_fp16<2>, cudaFuncAttributeMaxDynamicSharedMemorySize, SMEM_F);

#define SYM(p, s) do { void* _t; cudaGetSymbolAddress(&_t, s); p = (decltype(p))_t; } while (0)
    __half *h1, *h2t, *pp, *qs, *v, *w2, *w3, *pw2, *wv, *wo;
    float *h2, *amp, *phs;
    SYM(h1, g_h1);   SYM(h2, g_h2);   SYM(h2t, g_h2t);
    SYM(pp, g_p);    SYM(amp, g_amp); SYM(phs, g_phs);
    SYM(qs, g_qs);   SYM(v, g_v);
    SYM(w2, g_w2);   SYM(w3, g_w3);   SYM(pw2, g_pw2);
    SYM(wv, g_wv);   SYM(wo, g_wo);
#undef SYM

    moments_kernel<<<1, 256>>>(amp_W1, amp_b1, N1, 0);
    moments_kernel<<<1, 256>>>(ph_W1,  ph_b1,  N2, 1);

    {
        int n8;
        n8 = N2 * N1 / 8;     conv_fp16<<<(n8 + 255) / 256, 256>>>(amp_W2, w2, n8);
        n8 = QDIM * N2 / 8;   conv_fp16<<<(n8 + 255) / 256, 256>>>(amp_W3, w3, n8);
        n8 = QDIM * N2 / 8;   conv_fp16<<<(n8 + 255) / 256, 256>>>(ph_W2, pw2, n8);
        n8 = QDIM * QDIM / 8; conv_fp16<<<(n8 + 255) / 256, 256>>>(
            attn_in_w + (size_t)2 * QDIM * QDIM, wv, n8);
        n8 = QDIM * QDIM / 8; conv_fp16<<<(n8 + 255) / 256, 256>>>(attn_out_w, wo, n8);
    }

    layer1_kernel<<<(BATCH * (N1 / 4) + 255) / 256, 256>>>(
        x, amp_W1, amp_b1, amp_g1, amp_be1, h1, N1, 0, 0);
    layer1_kernel<<<(BATCH * (N2 / 4) + 255) / 256, 256>>>(
        x, ph_W1, ph_b1, ph_g1, ph_be1, pp, N2, 1, 1);

    // GEMM1: h2 = h1 @ W2^T + b2 (fp32 out)
    gemm_run(0, h1, w2, amp_b2, h2, nullptr, N2, N1);
    ln_tanh_rows<<<BATCH, 256>>>(h2, amp_g2, amp_be2, h2t);
    // GEMM2: amp = h2t @ W3^T + b3
    gemm_run(0, h2t, w3, amp_b3, amp, nullptr, QDIM, N2);
    // GEMM3: phase = tanh(p @ phW2^T + b2)
    gemm_run(1, pp, pw2, ph_b2, phs, nullptr, QDIM, N2);
    // qs mix
    qs_kernel<<<(BATCH * (QDIM / 4) + 255) / 256, 256>>>(amp, phs, rot_freq, rot_phase, qs);
    // GEMM4: v = qs @ Wv^T + bv (fp16 out)
    gemm_run(2, qs, wv, attn_in_b + 2 * QDIM, nullptr, v, QDIM, QDIM);
    // GEMM5: out = v @ Wout^T + bout
    gemm_run(0, v, wo, attn_out_b, out, nullptr, QDIM, QDIM);
}

// round 16
// speedup vs baseline: 1.4717x; 1.4717x over previous
#include <cuda_runtime.h>
#include <cuda_fp16.h>
#include <math.h>
#include <stdint.h>

#define BATCH 16384
#define QDIM  1024
#define N1    4096
#define N2    2048

// ---------------------------------------------------------------------------
// Scratch (device globals — allocation-free rule)
// ---------------------------------------------------------------------------
__device__ float  g_stats[2][9];
__device__ __half g_h1 [(size_t)BATCH * N1];
__device__ float  g_h2 [(size_t)BATCH * N2];
__device__ __half g_h2t[(size_t)BATCH * N2];
__device__ __half g_p  [(size_t)BATCH * N2];
__device__ float  g_amp[(size_t)BATCH * QDIM];
__device__ float  g_phs[(size_t)BATCH * QDIM];
__device__ __half g_qs [(size_t)BATCH * QDIM];
__device__ __half g_w2 [(size_t)N2 * N1];
__device__ __half g_w3 [(size_t)QDIM * N2];
__device__ __half g_pw2[(size_t)QDIM * N2];
__device__ __half g_wvT[(size_t)QDIM * QDIM];   // Wv^T (fp16)
__device__ __half g_wo [(size_t)QDIM * QDIM];   // Wo (fp16)
__device__ __half g_wc [(size_t)QDIM * QDIM];   // Wc = Wo @ Wv (fp16)
__device__ float  g_bc [QDIM];                  // bc = bo + Wo·bv (fp32, exact)

// ---------------------------------------------------------------------------
// Helpers
// ---------------------------------------------------------------------------
__device__ __forceinline__ uint32_t smem_u32(const void* p) {
    uint32_t a;
    asm("{ .reg .u64 t; cvta.to.shared.u64 t, %1; cvt.u32.u64 %0, t; }"
        : "=r"(a) : "l"(p));
    return a;
}
__device__ __forceinline__ size_t gaddr(const void* p) {
    size_t r;
    asm("cvta.to.global.u64 %0, %1;" : "=l"(r) : "l"(p));
    return r;
}
static __device__ __forceinline__ uint32_t swz128(uint32_t x) {
    return x ^ ((x >> 3) & 0x70);
}

// ---------------------------------------------------------------------------
// Single-pass fp16 GEMM via mma.sync (HMMA) — PROVEN R13 CONFIG:
//   C[M,N] = A[M,K] @ B[N,K]^T + bias, fp32 accumulate.
// CTA 128x128, 8 warps (64x32 warp tiles), BK=64, 3-stage cp.async ring
// (96 KB -> 2 CTAs/SM), single barrier per K-chunk, B via paired ldmatrix.x4.
// EPI: 0 = fp32 out, 1 = tanh fp32 out, 2 = fp16 out.
// ---------------------------------------------------------------------------
#define BM 128
#define BN 128
#define BK 64
#define TILE_B (BM * BK * 2)       // 16384 bytes per tile
#define STG_B  (2 * TILE_B)        // 32768: A | B
#define NSTG   3
#define SMEM_F (NSTG * STG_B)      // 98304

template <int EPI>
__global__ __launch_bounds__(256)
void gemm_fp16(const __half* __restrict__ A, const __half* __restrict__ B,
               const float* __restrict__ bias,
               float* __restrict__ Cf, __half* __restrict__ Ch,
               int Ntot, int K) {
    extern __shared__ char smem[];
    uint32_t sbase = smem_u32(smem);
    int tid = threadIdx.x, lane = tid & 31, wid = tid >> 5;
    int bm = blockIdx.y * BM, bn = blockIdx.x * BN;
    int wm = (wid >> 2) * 64, wn = (wid & 3) * 32;

    const int nIt = K / BK;

    float acc[16][4];
#pragma unroll
    for (int i = 0; i < 16; i++)
#pragma unroll
        for (int j = 0; j < 4; j++) acc[i][j] = 0.f;

    int lrow = tid >> 3;        // 0..31 base row; +32*i
    int lcol = (tid & 7) * 16;  // byte column within 128B row

    auto issue_stage = [&](int it, int stage) {
        uint32_t sb = sbase + stage * STG_B;
        int kb = it * BK + (tid & 7) * 8;   // element offset in K
#pragma unroll
        for (int i = 0; i < 4; i++) {
            int row = lrow + i * 32;
            uint32_t off = swz128((uint32_t)(row * 128 + lcol));
            size_t g0 = gaddr(A + (size_t)(bm + row) * K + kb);
            size_t g1 = gaddr(B + (size_t)(bn + row) * K + kb);
            asm volatile("cp.async.cg.shared.global [%0], [%1], 16;"
                         :: "r"(sb + off), "l"(g0));
            asm volatile("cp.async.cg.shared.global [%0], [%1], 16;"
                         :: "r"(sb + TILE_B + off), "l"(g1));
        }
        asm volatile("cp.async.commit_group;" ::: "memory");
    };

    issue_stage(0, 0);
    if (nIt > 1) issue_stage(1, 1);

    for (int it = 0; it < nIt; it++) {
        if (it + 1 < nIt) {
            asm volatile("cp.async.wait_group 1;" ::: "memory");
        } else {
            asm volatile("cp.async.wait_group 0;" ::: "memory");
        }
        __syncthreads();     // stage `it` visible; all threads done with it-1
        if (it + 2 < nIt) issue_stage(it + 2, (it + 2) % NSTG);  // slot (it-1)%3 — safe

        uint32_t sA = sbase + (it % NSTG) * STG_B;
        uint32_t sB = sA + TILE_B;

#pragma unroll
        for (int ks = 0; ks < 4; ks++) {
            uint32_t a[4][4], b[4][2];
#pragma unroll
            for (int mi = 0; mi < 4; mi++) {
                int row = wm + mi * 16 + (lane & 15);
                uint32_t off = swz128((uint32_t)(row * 128 + ks * 32 + (lane >> 4) * 16));
                asm volatile("ldmatrix.sync.aligned.m8n8.x4.shared.b16 {%0,%1,%2,%3}, [%4];"
                             : "=r"(a[mi][0]), "=r"(a[mi][1]), "=r"(a[mi][2]), "=r"(a[mi][3])
                             : "r"(sA + off));
            }
            // B: one x4 per pair of n-groups
#pragma unroll
            for (int np = 0; np < 2; np++) {
                int row = wn + np * 16 + ((lane >> 4) & 1) * 8 + (lane & 7);
                uint32_t off = swz128((uint32_t)(row * 128 + ks * 32 + ((lane >> 3) & 1) * 16));
                asm volatile("ldmatrix.sync.aligned.m8n8.x4.shared.b16 {%0,%1,%2,%3}, [%4];"
                             : "=r"(b[2 * np][0]), "=r"(b[2 * np][1]),
                               "=r"(b[2 * np + 1][0]), "=r"(b[2 * np + 1][1])
                             : "r"(sB + off));
            }
#pragma unroll
            for (int mi = 0; mi < 4; mi++)
#pragma unroll
                for (int ni = 0; ni < 4; ni++) {
                    float* c = acc[mi * 4 + ni];
                    asm volatile(
                        "mma.sync.aligned.m16n8k16.row.col.f32.f16.f16.f32 "
                        "{%0,%1,%2,%3}, {%4,%5,%6,%7}, {%8,%9}, {%0,%1,%2,%3};"
                        : "+f"(c[0]), "+f"(c[1]), "+f"(c[2]), "+f"(c[3])
                        : "r"(a[mi][0]), "r"(a[mi][1]), "r"(a[mi][2]), "r"(a[mi][3]),
                          "r"(b[ni][0]), "r"(b[ni][1]));
                }
        }
        // no bottom barrier (3-stage ring)
    }

    // epilogue
    int mb = bm + wm, nb = bn + wn;
#pragma unroll
    for (int mi = 0; mi < 4; mi++)
#pragma unroll
        for (int ni = 0; ni < 4; ni++) {
            float* c = acc[mi * 4 + ni];
            int r0 = mb + mi * 16 + (lane >> 2);
            int c0 = nb + ni * 8 + (lane & 3) * 2;
            float b0 = __ldg(bias + c0), b1 = __ldg(bias + c0 + 1);
            float y0 = c[0] + b0, y1 = c[1] + b1;
            float y2 = c[2] + b0, y3 = c[3] + b1;
            if (EPI == 1) {
                y0 = tanhf(y0); y1 = tanhf(y1); y2 = tanhf(y2); y3 = tanhf(y3);
            }
            if (EPI == 2) {
                __half2 p0; p0.x = __float2half(y0); p0.y = __float2half(y1);
                __half2 p1; p1.x = __float2half(y2); p1.y = __float2half(y3);
                *(__half2*)(Ch + (size_t)r0 * Ntot + c0)       = p0;
                *(__half2*)(Ch + (size_t)(r0 + 8) * Ntot + c0) = p1;
            } else {
                *(float2*)(Cf + (size_t)r0 * Ntot + c0)       = make_float2(y0, y1);
                *(float2*)(Cf + (size_t)(r0 + 8) * Ntot + c0) = make_float2(y2, y3);
            }
        }
}

// ---------------------------------------------------------------------------
// Weight convert: fp32 -> fp16 (8 elems/thread, 16B store)
// ---------------------------------------------------------------------------
__global__ void conv_fp16(const float* __restrict__ in, __half* __restrict__ out, int n8) {
    int i = blockIdx.x * blockDim.x + threadIdx.x;
    if (i >= n8) return;
    float4 v0 = *(const float4*)(in + 8 * i);
    float4 v1 = *(const float4*)(in + 8 * i + 4);
    __half2 h[4];
    h[0].x = __float2half(v0.x); h[0].y = __float2half(v0.y);
    h[1].x = __float2half(v0.z); h[1].y = __float2half(v0.w);
    h[2].x = __float2half(v1.x); h[2].y = __float2half(v1.y);
    h[3].x = __float2half(v1.z); h[3].y = __float2half(v1.w);
    *(uint4*)(out + 8 * i) = *(uint4*)h;
}

// Transposed convert: out[j*R + n] = in[n*C + j] as fp16 (for Wv^T).
// R = rows of in (n-dim), C = cols of in (j-dim). 32x32 smem tiles.
__global__ void conv_fp16_T(const float* __restrict__ in, __half* __restrict__ out,
                            int R, int C) {
    __shared__ float tile[32][33];
    int bx = blockIdx.x * 32, by = blockIdx.y * 32;
    int tx = threadIdx.x, ty = threadIdx.y;
    // read in[by+ty.. , bx+tx]  (rows n, cols j)
    for (int dy = 0; dy < 32; dy += 8) {
        int n = by + ty + dy, j = bx + tx;
        if (n < R && j < C) tile[ty + dy][tx] = in[(size_t)n * C + j];
    }
    __syncthreads();
    // write out[(bx+ty+dy)*R + by+tx] = tile[tx][ty+dy]
    for (int dy = 0; dy < 32; dy += 8) {
        int j = bx + ty + dy, n = by + tx;
        if (j < C && n < R) out[(size_t)j * R + n] = __float2half(tile[tx][ty + dy]);
    }
}

// bc[i] = bo[i] + sum_n Wo[i,n] * bv[n]   (fp32, exact)
__global__ void bias_fuse(const float* __restrict__ Wo, const float* __restrict__ bv,
                          const float* __restrict__ bo, float* __restrict__ bc) {
    int i = blockIdx.x * blockDim.x + threadIdx.x;
    if (i >= QDIM) return;
    float s = 0.f;
    const float* row = Wo + (size_t)i * QDIM;
    for (int n = 0; n < QDIM; n += 4) {
        float4 w = *(const float4*)(row + n);
        float4 b = *(const float4*)(bv + n);
        s += w.x * b.x + w.y * b.y + w.z * b.z + w.w * b.w;
    }
    bc[i] = bo[i] + s;
}

// ---------------------------------------------------------------------------
// Moments for the F=2 closed-form LN
// ---------------------------------------------------------------------------
__global__ void moments_kernel(const float* __restrict__ W,
                               const float* __restrict__ bv, int N, int which) {
    int tid = threadIdx.x;
    double acc[9];
#pragma unroll
    for (int q = 0; q < 9; q++) acc[q] = 0.0;
    for (int j = tid; j < N; j += 256) {
        double w0 = W[2 * j], w1 = W[2 * j + 1], b = bv[j];
        acc[0] += w0;      acc[1] += w1;      acc[2] += b;
        acc[3] += w0 * w0; acc[4] += w1 * w1; acc[5] += b * b;
        acc[6] += w0 * w1; acc[7] += w0 * b;  acc[8] += w1 * b;
    }
    __shared__ double sd[256];
    for (int q = 0; q < 9; q++) {
        sd[tid] = acc[q];
        __syncthreads();
        for (int s = 128; s > 0; s >>= 1) {
            if (tid < s) sd[tid] += sd[tid + s];
            __syncthreads();
        }
        if (tid == 0) g_stats[which][q] = (float)(sd[0] / N);
        __syncthreads();
    }
}

// ---------------------------------------------------------------------------
// Layer-1 (elementwise, closed-form LN) -> fp16. act: 0=gelu, 1=silu
// ---------------------------------------------------------------------------
__global__ void layer1_kernel(const float* __restrict__ x, const float* __restrict__ W,
                              const float* __restrict__ bv, const float* __restrict__ gam,
                              const float* __restrict__ bet,
                              __half* __restrict__ oh,
                              int N, int which, int act) {
    int nv = N >> 2;
    int i = blockIdx.x * blockDim.x + threadIdx.x;
    if (i >= BATCH * nv) return;
    int b = i / nv;
    int j = (i - b * nv) << 2;

    float x0 = __ldg(x + 2 * b), x1 = __ldg(x + 2 * b + 1);
    const float* s = g_stats[which];
    float m  = x0 * s[0] + x1 * s[1] + s[2];
    float E2 = x0 * x0 * s[3] + x1 * x1 * s[4] + s[5]
             + 2.f * (x0 * x1 * s[6] + x0 * s[7] + x1 * s[8]);
    float rstd = rsqrtf(fmaxf(E2 - m * m, 0.f) + 1e-5f);

    float4 wA = *(const float4*)(W + 2 * j);
    float4 wB = *(const float4*)(W + 2 * j + 4);
    float4 bb = *(const float4*)(bv + j);
    float4 gg = *(const float4*)(gam + j);
    float4 ee = *(const float4*)(bet + j);

    float y[4];
    y[0] = x0 * wA.x + x1 * wA.y + bb.x;
    y[1] = x0 * wA.z + x1 * wA.w + bb.y;
    y[2] = x0 * wB.x + x1 * wB.y + bb.z;
    y[3] = x0 * wB.z + x1 * wB.w + bb.w;
    float gv[4] = {gg.x, gg.y, gg.z, gg.w};
    float ev[4] = {ee.x, ee.y, ee.z, ee.w};

    __half2 o01, o23;
    float o[4];
#pragma unroll
    for (int q = 0; q < 4; q++) {
        float t = (y[q] - m) * rstd * gv[q] + ev[q];
        if (act == 0) o[q] = 0.5f * t * (1.0f + erff(t * 0.70710678118654752f));
        else          o[q] = t / (1.0f + expf(-t));
    }
    o01.x = __float2half(o[0]); o01.y = __float2half(o[1]);
    o23.x = __float2half(o[2]); o23.y = __float2half(o[3]);
    size_t base = (size_t)b * N + j;
    *(__half2*)(oh + base)     = o01;
    *(__half2*)(oh + base + 2) = o23;
}

// ---------------------------------------------------------------------------
// Row LayerNorm + tanh over N=2048, fp32 in -> fp16 out
// ---------------------------------------------------------------------------
__global__ void ln_tanh_rows(const float* __restrict__ data,
                             const float* __restrict__ gam, const float* __restrict__ bet,
                             __half* __restrict__ oh) {
    const int N = 2048;
    int row = blockIdx.x, tid = threadIdx.x;
    const float* p = data + (size_t)row * N;

    float v[8], s = 0.f, s2 = 0.f;
#pragma unroll
    for (int i = 0; i < 8; i++) {
        float t = p[tid + i * 256];
        v[i] = t; s += t; s2 += t * t;
    }
#pragma unroll
    for (int o = 16; o > 0; o >>= 1) {
        s  += __shfl_down_sync(0xffffffffu, s, o);
        s2 += __shfl_down_sync(0xffffffffu, s2, o);
    }
    __shared__ float sh[2][8];
    __shared__ float mb[2];
    int w = tid >> 5, l = tid & 31;
    if (l == 0) { sh[0][w] = s; sh[1][w] = s2; }
    __syncthreads();
    if (tid == 0) {
        float S = 0.f, S2 = 0.f;
#pragma unroll
        for (int q = 0; q < 8; q++) { S += sh[0][q]; S2 += sh[1][q]; }
        float mean = S / N;
        mb[0] = mean;
        mb[1] = rsqrtf(fmaxf(S2 / N - mean * mean, 0.f) + 1e-5f);
    }
    __syncthreads();
    float mean = mb[0], rstd = mb[1];
    size_t base = (size_t)row * N;
#pragma unroll
    for (int i = 0; i < 8; i++) {
        int c = tid + i * 256;
        float t = tanhf((v[i] - mean) * rstd * gam[c] + bet[c]);
        oh[base + c] = __float2half(t);
    }
}

// ---------------------------------------------------------------------------
// qs mix, fp32 amp/phase in -> fp16 out
// ---------------------------------------------------------------------------
__global__ void qs_kernel(const float* __restrict__ amp, const float* __restrict__ phase,
                          const float* __restrict__ rot_freq, const float* __restrict__ rot_phase,
                          __half* __restrict__ qh) {
    int i = blockIdx.x * blockDim.x + threadIdx.x;
    if (i >= BATCH * (QDIM / 4)) return;
    int j = (i & (QDIM / 4 - 1)) << 2;
    float4 a  = *(const float4*)(amp + (size_t)i * 4);
    float4 ph = *(const float4*)(phase + (size_t)i * 4);
    const float* rf = rot_freq  + (size_t)(4 * QDIM + j) * 3;
    const float* rp = rot_phase + (size_t)(4 * QDIM + j) * 3;
    float av[4] = {a.x, a.y, a.z, a.w};
    float pv[4] = {ph.x, ph.y, ph.z, ph.w};
    float o[4];
#pragma unroll
    for (int q = 0; q < 4; q++) {
        float rx = sinf(av[q] * rf[3 * q + 0] + rp[3 * q + 0]);
        float ry = cosf(pv[q] * rf[3 * q + 1] + rp[3 * q + 1]);
        float rz = tanhf(rp[3 * q + 2]);
        o[q] = (rx + ry + rz) * (1.0f / 3.0f);
    }
    __half2 o01, o23;
    o01.x = __float2half(o[0]); o01.y = __float2half(o[1]);
    o23.x = __float2half(o[2]); o23.y = __float2half(o[3]);
    *(__half2*)(qh + (size_t)i * 4)     = o01;
    *(__half2*)(qh + (size_t)i * 4 + 2) = o23;
}

// ---------------------------------------------------------------------------
// Launch
// ---------------------------------------------------------------------------
static void gemm_run(int epi, const __half* A, const __half* B,
                     const float* bias, float* Cf, __half* Ch,
                     int M, int Ntot, int K) {
    dim3 g(Ntot / BN, M / BM);
    switch (epi) {
    case 0:  gemm_fp16<0><<<g, 256, SMEM_F>>>(A, B, bias, Cf, Ch, Ntot, K); break;
    case 1:  gemm_fp16<1><<<g, 256, SMEM_F>>>(A, B, bias, Cf, Ch, Ntot, K); break;
    default: gemm_fp16<2><<<g, 256, SMEM_F>>>(A, B, bias, Cf, Ch, Ntot, K); break;
    }
}

__device__ float g_zero_bias[QDIM];   // stays zero (device globals zero-init)

extern "C" void kernel_launch(void* const* d_in, const int* in_sizes, int n_in,
                              void* d_out, int out_size) {
    const float* x         = (const float*)d_in[0];
    const float* amp_W1    = (const float*)d_in[1];
    const float* amp_b1    = (const float*)d_in[2];
    const float* amp_g1    = (const float*)d_in[3];
    const float* amp_be1   = (const float*)d_in[4];
    const float* amp_W2    = (const float*)d_in[5];
    const float* amp_b2    = (const float*)d_in[6];
    const float* amp_g2    = (const float*)d_in[7];
    const float* amp_be2   = (const float*)d_in[8];
    const float* amp_W3    = (const float*)d_in[9];
    const float* amp_b3    = (const float*)d_in[10];
    const float* ph_W1     = (const float*)d_in[11];
    const float* ph_b1     = (const float*)d_in[12];
    const float* ph_g1     = (const float*)d_in[13];
    const float* ph_be1    = (const float*)d_in[14];
    const float* ph_W2     = (const float*)d_in[15];
    const float* ph_b2     = (const float*)d_in[16];
    const float* rot_freq  = (const float*)d_in[17];
    const float* rot_phase = (const float*)d_in[18];
    const float* attn_in_w = (const float*)d_in[19];
    const float* attn_in_b = (const float*)d_in[20];
    const float* attn_out_w= (const float*)d_in[21];
    const float* attn_out_b= (const float*)d_in[22];
    float* out = (float*)d_out;

    cudaFuncSetAttribute(gemm_fp16<0>, cudaFuncAttributeMaxDynamicSharedMemorySize, SMEM_F);
    cudaFuncSetAttribute(gemm_fp16<1>, cudaFuncAttributeMaxDynamicSharedMemorySize, SMEM_F);
    cudaFuncSetAttribute(gemm_fp16<2>, cudaFuncAttributeMaxDynamicSharedMemorySize, SMEM_F);

#define SYM(p, s) do { void* _t; cudaGetSymbolAddress(&_t, s); p = (decltype(p))_t; } while (0)
    __half *h1, *h2t, *pp, *qs, *w2, *w3, *pw2, *wvT, *wo, *wc;
    float *h2, *amp, *phs, *bc, *zb;
    SYM(h1, g_h1);   SYM(h2, g_h2);   SYM(h2t, g_h2t);
    SYM(pp, g_p);    SYM(amp, g_amp); SYM(phs, g_phs);
    SYM(qs, g_qs);
    SYM(w2, g_w2);   SYM(w3, g_w3);   SYM(pw2, g_pw2);
    SYM(wvT, g_wvT); SYM(wo, g_wo);   SYM(wc, g_wc);
    SYM(bc, g_bc);   SYM(zb, g_zero_bias);
#undef SYM

    moments_kernel<<<1, 256>>>(amp_W1, amp_b1, N1, 0);
    moments_kernel<<<1, 256>>>(ph_W1,  ph_b1,  N2, 1);

    {
        int n8;
        n8 = N2 * N1 / 8;     conv_fp16<<<(n8 + 255) / 256, 256>>>(amp_W2, w2, n8);
        n8 = QDIM * N2 / 8;   conv_fp16<<<(n8 + 255) / 256, 256>>>(amp_W3, w3, n8);
        n8 = QDIM * N2 / 8;   conv_fp16<<<(n8 + 255) / 256, 256>>>(ph_W2, pw2, n8);
        n8 = QDIM * QDIM / 8; conv_fp16<<<(n8 + 255) / 256, 256>>>(attn_out_w, wo, n8);
        // Wv^T: wvT[j, n] = attn_in_w[2Q + n, j]
        dim3 tb(32, 8), tg(QDIM / 32, QDIM / 32);
        conv_fp16_T<<<tg, tb>>>(attn_in_w + (size_t)2 * QDIM * QDIM, wvT, QDIM, QDIM);
        // bc = bo + Wo·bv (exact fp32)
        bias_fuse<<<(QDIM + 255) / 256, 256>>>(attn_out_w, attn_in_b + 2 * QDIM,
                                               attn_out_b, bc);
        // Wc[i,j] = sum_n Wo[i,n]·WvT[j,n]  -> fp16 out (tiny GEMM, M=N=K=1024)
        gemm_run(2, wo, wvT, zb, nullptr, wc, QDIM, QDIM, QDIM);
    }

    layer1_kernel<<<(BATCH * (N1 / 4) + 255) / 256, 256>>>(
        x, amp_W1, amp_b1, amp_g1, amp_be1, h1, N1, 0, 0);
    layer1_kernel<<<(BATCH * (N2 / 4) + 255) / 256, 256>>>(
        x, ph_W1, ph_b1, ph_g1, ph_be1, pp, N2, 1, 1);

    // GEMM1: h2 = h1 @ W2^T + b2 (fp32 out)
    gemm_run(0, h1, w2, amp_b2, h2, nullptr, BATCH, N2, N1);
    ln_tanh_rows<<<BATCH, 256>>>(h2, amp_g2, amp_be2, h2t);
    // GEMM2: amp = h2t @ W3^T + b3
    gemm_run(0, h2t, w3, amp_b3, amp, nullptr, BATCH, QDIM, N2);
    // GEMM3: phase = tanh(p @ phW2^T + b2)
    gemm_run(1, pp, pw2, ph_b2, phs, nullptr, BATCH, QDIM, N2);
    // qs mix
    qs_kernel<<<(BATCH * (QDIM / 4) + 255) / 256, 256>>>(amp, phs, rot_freq, rot_phase, qs);
    // Fused GEMM4+5: out = qs @ Wc^T + bc
    gemm_run(0, qs, wc, bc, out, nullptr, BATCH, QDIM, QDIM);
}